// round 1
// baseline (speedup 1.0000x reference)
#include <cuda_runtime.h>
#include <math.h>

#define SQ 2048
#define DM 1024
#define NH 16
#define DH 64
#define NB 2
#define BH 32          // NB*NH
#define MTOT 4096      // NB*SQ

// Scratch (allocation-free: device globals). 4 x 16 MB.
__device__ float g_qh[BH * SQ * DH];
__device__ float g_kh[BH * SQ * DH];
__device__ float g_vh[BH * SQ * DH];
__device__ float g_ctx[BH * SQ * DH];

// ---------------------------------------------------------------------------
// Projection GEMM: Y[m,n] = sum_k A[m,k]*W[n,k] + bias[n]
// A_IS_CTX: A is stored as ctx[b,h,s,dh] (head layout), logical [M=4096, K=1024]
// OUT_HEADS: write Y into head layout [b,h,s,dh] instead of [m,n]
// Tile: 128x128x8, 256 threads, 8x8 per thread.
// ---------------------------------------------------------------------------
template<bool A_IS_CTX, bool OUT_HEADS>
__global__ __launch_bounds__(256) void gemm_proj(
    const float* __restrict__ A, const float* __restrict__ W,
    const float* __restrict__ bias, float* __restrict__ out)
{
    const int K = DM, N = DM;
    __shared__ float As[8][128];
    __shared__ float Bs[8][128];
    int tid = threadIdx.x;
    int m0 = blockIdx.y * 128;
    int n0 = blockIdx.x * 128;
    int tx = tid & 15, ty = tid >> 4;
    int lr = tid >> 1;
    int lc = (tid & 1) * 4;

    float acc[8][8];
#pragma unroll
    for (int i = 0; i < 8; i++)
#pragma unroll
        for (int j = 0; j < 8; j++) acc[i][j] = 0.f;

    for (int k0 = 0; k0 < K; k0 += 8) {
        float4 a4;
        if (A_IS_CTX) {
            int m = m0 + lr, k = k0 + lc;
            int b = m >> 11, s = m & 2047, h = k >> 6, dh = k & 63;
            a4 = *(const float4*)&A[(((size_t)(b * NH + h) * SQ + s) * DH) + dh];
        } else {
            a4 = *(const float4*)&A[(size_t)(m0 + lr) * K + k0 + lc];
        }
        float4 b4 = *(const float4*)&W[(size_t)(n0 + lr) * K + k0 + lc];
        As[lc + 0][lr] = a4.x; As[lc + 1][lr] = a4.y;
        As[lc + 2][lr] = a4.z; As[lc + 3][lr] = a4.w;
        Bs[lc + 0][lr] = b4.x; Bs[lc + 1][lr] = b4.y;
        Bs[lc + 2][lr] = b4.z; Bs[lc + 3][lr] = b4.w;
        __syncthreads();
#pragma unroll
        for (int k = 0; k < 8; k++) {
            float ra[8], rb[8];
            *(float4*)&ra[0] = *(const float4*)&As[k][ty * 8];
            *(float4*)&ra[4] = *(const float4*)&As[k][ty * 8 + 4];
            *(float4*)&rb[0] = *(const float4*)&Bs[k][tx * 8];
            *(float4*)&rb[4] = *(const float4*)&Bs[k][tx * 8 + 4];
#pragma unroll
            for (int i = 0; i < 8; i++)
#pragma unroll
                for (int j = 0; j < 8; j++)
                    acc[i][j] += ra[i] * rb[j];
        }
        __syncthreads();
    }

#pragma unroll
    for (int i = 0; i < 8; i++) {
        int m = m0 + ty * 8 + i;
#pragma unroll
        for (int j = 0; j < 8; j++) {
            int n = n0 + tx * 8 + j;
            float val = acc[i][j] + bias[n];
            if (OUT_HEADS) {
                int b = m >> 11, s = m & 2047, h = n >> 6, dh = n & 63;
                out[(((size_t)(b * NH + h) * SQ + s) * DH) + dh] = val;
            } else {
                out[(size_t)m * N + n] = val;
            }
        }
    }
}

// ---------------------------------------------------------------------------
// Logits: attn_raw[bh,q,k] = (qh . kh)/8 + mask[b,k]*-1e9  (raw, pre-softmax)
// Batched GEMM, K=64. Tile 128x128x8.
// ---------------------------------------------------------------------------
__global__ __launch_bounds__(256) void logits_kernel(
    const float* __restrict__ mask, float* __restrict__ attn)
{
    __shared__ float As[8][128];
    __shared__ float Bs[8][128];
    int bh = blockIdx.z;
    const float* A  = g_qh + (size_t)bh * SQ * DH;
    const float* Bm = g_kh + (size_t)bh * SQ * DH;
    int tid = threadIdx.x;
    int m0 = blockIdx.y * 128;
    int n0 = blockIdx.x * 128;
    int tx = tid & 15, ty = tid >> 4;
    int lr = tid >> 1;
    int lc = (tid & 1) * 4;

    float acc[8][8];
#pragma unroll
    for (int i = 0; i < 8; i++)
#pragma unroll
        for (int j = 0; j < 8; j++) acc[i][j] = 0.f;

    for (int k0 = 0; k0 < DH; k0 += 8) {
        float4 a4 = *(const float4*)&A[(size_t)(m0 + lr) * DH + k0 + lc];
        float4 b4 = *(const float4*)&Bm[(size_t)(n0 + lr) * DH + k0 + lc];
        As[lc + 0][lr] = a4.x; As[lc + 1][lr] = a4.y;
        As[lc + 2][lr] = a4.z; As[lc + 3][lr] = a4.w;
        Bs[lc + 0][lr] = b4.x; Bs[lc + 1][lr] = b4.y;
        Bs[lc + 2][lr] = b4.z; Bs[lc + 3][lr] = b4.w;
        __syncthreads();
#pragma unroll
        for (int k = 0; k < 8; k++) {
            float ra[8], rb[8];
            *(float4*)&ra[0] = *(const float4*)&As[k][ty * 8];
            *(float4*)&ra[4] = *(const float4*)&As[k][ty * 8 + 4];
            *(float4*)&rb[0] = *(const float4*)&Bs[k][tx * 8];
            *(float4*)&rb[4] = *(const float4*)&Bs[k][tx * 8 + 4];
#pragma unroll
            for (int i = 0; i < 8; i++)
#pragma unroll
                for (int j = 0; j < 8; j++)
                    acc[i][j] += ra[i] * rb[j];
        }
        __syncthreads();
    }

    const float* mrow = mask + (size_t)(bh >> 4) * SQ;
#pragma unroll
    for (int i = 0; i < 8; i++) {
        int m = m0 + ty * 8 + i;
#pragma unroll
        for (int j = 0; j < 8; j++) {
            int n = n0 + tx * 8 + j;
            attn[((size_t)bh * SQ + m) * SQ + n] =
                acc[i][j] * 0.125f + mrow[n] * (-1e9f);
        }
    }
}

// ---------------------------------------------------------------------------
// Row softmax in place: one block (256 threads) per row of 2048.
// ---------------------------------------------------------------------------
__global__ __launch_bounds__(256) void softmax_kernel(float* __restrict__ attn)
{
    size_t row = blockIdx.x;
    float* p = attn + row * SQ;
    int tid = threadIdx.x;
    int w = tid >> 5, l = tid & 31;
    __shared__ float smax[8];
    __shared__ float ssum[8];

    float v[8];
#pragma unroll
    for (int i = 0; i < 8; i++) v[i] = p[i * 256 + tid];

    float mx = -INFINITY;
#pragma unroll
    for (int i = 0; i < 8; i++) mx = fmaxf(mx, v[i]);
#pragma unroll
    for (int o = 16; o > 0; o >>= 1)
        mx = fmaxf(mx, __shfl_xor_sync(0xffffffffu, mx, o));
    if (l == 0) smax[w] = mx;
    __syncthreads();
    mx = smax[0];
#pragma unroll
    for (int i = 1; i < 8; i++) mx = fmaxf(mx, smax[i]);

    float e[8];
    float sum = 0.f;
#pragma unroll
    for (int i = 0; i < 8; i++) { e[i] = __expf(v[i] - mx); sum += e[i]; }
#pragma unroll
    for (int o = 16; o > 0; o >>= 1)
        sum += __shfl_xor_sync(0xffffffffu, sum, o);
    if (l == 0) ssum[w] = sum;
    __syncthreads();
    float tot = 0.f;
#pragma unroll
    for (int i = 0; i < 8; i++) tot += ssum[i];
    float inv = 1.f / tot;
#pragma unroll
    for (int i = 0; i < 8; i++) p[i * 256 + tid] = e[i] * inv;
}

// ---------------------------------------------------------------------------
// AV: ctx[bh, m, n] = sum_k attn[bh, m, k] * vh[bh, k, n]
// Tile 128x64x16, 256 threads, 8x4 per thread. attn read exactly once.
// ---------------------------------------------------------------------------
__global__ __launch_bounds__(256) void av_kernel(const float* __restrict__ attn)
{
    __shared__ float As[16][128];
    __shared__ float Bs[16][64];
    int bh = blockIdx.z;
    const float* A = attn + (size_t)bh * SQ * SQ;
    const float* V = g_vh + (size_t)bh * SQ * DH;
    int tid = threadIdx.x;
    int m0 = blockIdx.y * 128;
    int tx = tid & 15, ty = tid >> 4;   // tx -> n (16*4=64), ty -> m (16*8=128)
    int ar = tid >> 2;                  // 0..63
    int ac = (tid & 3) * 4;             // 0,4,8,12
    int br = tid >> 4;                  // 0..15
    int bc = (tid & 15) * 4;            // 0..60

    float acc[8][4];
#pragma unroll
    for (int i = 0; i < 8; i++)
#pragma unroll
        for (int j = 0; j < 4; j++) acc[i][j] = 0.f;

    for (int k0 = 0; k0 < SQ; k0 += 16) {
        float4 a0 = *(const float4*)&A[(size_t)(m0 + ar) * SQ + k0 + ac];
        float4 a1 = *(const float4*)&A[(size_t)(m0 + ar + 64) * SQ + k0 + ac];
        float4 b4 = *(const float4*)&V[(size_t)(k0 + br) * DH + bc];
        As[ac + 0][ar] = a0.x; As[ac + 1][ar] = a0.y;
        As[ac + 2][ar] = a0.z; As[ac + 3][ar] = a0.w;
        As[ac + 0][ar + 64] = a1.x; As[ac + 1][ar + 64] = a1.y;
        As[ac + 2][ar + 64] = a1.z; As[ac + 3][ar + 64] = a1.w;
        *(float4*)&Bs[br][bc] = b4;
        __syncthreads();
#pragma unroll
        for (int k = 0; k < 16; k++) {
            float ra[8], rb[4];
            *(float4*)&ra[0] = *(const float4*)&As[k][ty * 8];
            *(float4*)&ra[4] = *(const float4*)&As[k][ty * 8 + 4];
            *(float4*)&rb[0] = *(const float4*)&Bs[k][tx * 4];
#pragma unroll
            for (int i = 0; i < 8; i++)
#pragma unroll
                for (int j = 0; j < 4; j++)
                    acc[i][j] += ra[i] * rb[j];
        }
        __syncthreads();
    }

    float* C = g_ctx + (size_t)bh * SQ * DH;
#pragma unroll
    for (int i = 0; i < 8; i++) {
        int m = m0 + ty * 8 + i;
#pragma unroll
        for (int j = 0; j < 4; j++)
            C[(size_t)m * DH + tx * 4 + j] = acc[i][j];
    }
}

// ---------------------------------------------------------------------------
extern "C" void kernel_launch(void* const* d_in, const int* in_sizes, int n_in,
                              void* d_out, int out_size)
{
    const float* q    = (const float*)d_in[0];
    const float* k    = (const float*)d_in[1];
    const float* v    = (const float*)d_in[2];
    const float* mask = (const float*)d_in[3];
    const float* wq   = (const float*)d_in[4];
    const float* bq   = (const float*)d_in[5];
    const float* wk   = (const float*)d_in[6];
    const float* bk   = (const float*)d_in[7];
    const float* wv   = (const float*)d_in[8];
    const float* bv   = (const float*)d_in[9];
    const float* wo   = (const float*)d_in[10];
    const float* bo   = (const float*)d_in[11];

    float* out  = (float*)d_out;                        // [B,S,D]
    float* attn = out + (size_t)NB * SQ * DM;           // [B,H,S,S]

    float *qh, *kh, *vh, *ctx;
    cudaGetSymbolAddress((void**)&qh,  g_qh);
    cudaGetSymbolAddress((void**)&kh,  g_kh);
    cudaGetSymbolAddress((void**)&vh,  g_vh);
    cudaGetSymbolAddress((void**)&ctx, g_ctx);

    dim3 gProj(DM / 128, MTOT / 128);       // (8, 32)
    gemm_proj<false, true><<<gProj, 256>>>(q, wq, bq, qh);
    gemm_proj<false, true><<<gProj, 256>>>(k, wk, bk, kh);
    gemm_proj<false, true><<<gProj, 256>>>(v, wv, bv, vh);

    dim3 gLog(SQ / 128, SQ / 128, BH);      // (16, 16, 32)
    logits_kernel<<<gLog, 256>>>(mask, attn);

    softmax_kernel<<<BH * SQ, 256>>>(attn); // 65536 rows

    dim3 gAV(1, SQ / 128, BH);              // (1, 16, 32)
    av_kernel<<<gAV, 256>>>(attn);

    gemm_proj<true, false><<<gProj, 256>>>(ctx, wo, bo, out);
}

// round 4
// speedup vs baseline: 1.3443x; 1.3443x over previous
#include <cuda_runtime.h>
#include <math.h>
#include <stdint.h>

#define SQ 2048
#define DM 1024
#define NH 16
#define DH 64
#define NB 2
#define BH 32          // NB*NH
#define MTOT 4096      // NB*SQ
#define PADQ 76        // smem row stride (floats) for attn kernels

// Scratch (allocation-free device globals)
__device__ float g_qh[BH * SQ * DH];
__device__ float g_kh[BH * SQ * DH];
__device__ float g_vh[BH * SQ * DH];
__device__ float g_ctx[BH * SQ * DH];
__device__ float g_rowsum[BH * SQ];

// ---------------------------------------------------------------------------
// tf32 helpers
// ---------------------------------------------------------------------------
__device__ __forceinline__ unsigned f2tf(float x) {
    unsigned u;
    asm("cvt.rna.tf32.f32 %0, %1;" : "=r"(u) : "f"(x));
    return u;
}

// D += A(16x8) * B(8x8), tf32 inputs, fp32 acc. Row-major A, col-major B.
__device__ __forceinline__ void mma_tf32(float* c, const unsigned* a,
                                         unsigned b0, unsigned b1) {
    asm volatile(
        "mma.sync.aligned.m16n8k8.row.col.f32.tf32.tf32.f32 "
        "{%0,%1,%2,%3},{%4,%5,%6,%7},{%8,%9},{%0,%1,%2,%3};\n"
        : "+f"(c[0]), "+f"(c[1]), "+f"(c[2]), "+f"(c[3])
        : "r"(a[0]), "r"(a[1]), "r"(a[2]), "r"(a[3]), "r"(b0), "r"(b1));
}

// ---------------------------------------------------------------------------
// Projection GEMM (tf32 split): Y[m,n] = sum_k A[m,k]*W[n,k] + bias[n]
// CTA 128x128, k-stage 16, 8 warps (2x4), warp tile 64x32.
// AH: A is head-layout ctx. OH: write Y to head layout.
// ---------------------------------------------------------------------------
template<bool AH, bool OH>
__global__ __launch_bounds__(256) void proj_tf32(
    const float* __restrict__ A, const float* __restrict__ W,
    const float* __restrict__ bias, float* __restrict__ out)
{
    __shared__ unsigned Ah[16][136], Al[16][136], Bh_[16][136], Bl_[16][136];
    int tid = threadIdx.x, wid = tid >> 5, lane = tid & 31;
    int g = lane >> 2, t = lane & 3;
    int wm0 = (wid >> 2) * 64, wn0 = (wid & 3) * 32;
    int m0 = blockIdx.y * 128, n0 = blockIdx.x * 128;
    int lr = tid >> 1, lc4 = (tid & 1) * 4;

    float acc[4][4][4];
#pragma unroll
    for (int i = 0; i < 4; i++)
#pragma unroll
        for (int j = 0; j < 4; j++)
#pragma unroll
            for (int l = 0; l < 4; l++) acc[i][j][l] = 0.f;

    // preload first k-chunk (16 cols: two float4 per operand per thread)
    float4 a4a, a4b, b4a, b4b;
    {
        int m = m0 + lr;
        if (AH) {
            int b = m >> 11, s = m & 2047;
            int k = lc4, h = k >> 6, dh = k & 63;
            a4a = *(const float4*)&A[(((size_t)(b * NH + h)) * SQ + s) * DH + dh];
            k = lc4 + 8; h = k >> 6; dh = k & 63;
            a4b = *(const float4*)&A[(((size_t)(b * NH + h)) * SQ + s) * DH + dh];
        } else {
            a4a = *(const float4*)&A[(size_t)m * DM + lc4];
            a4b = *(const float4*)&A[(size_t)m * DM + lc4 + 8];
        }
        b4a = *(const float4*)&W[(size_t)(n0 + lr) * DM + lc4];
        b4b = *(const float4*)&W[(size_t)(n0 + lr) * DM + lc4 + 8];
    }

    for (int k0 = 0; k0 < DM; k0 += 16) {
        // split + store current stage
        float av[8] = {a4a.x, a4a.y, a4a.z, a4a.w, a4b.x, a4b.y, a4b.z, a4b.w};
        float bv[8] = {b4a.x, b4a.y, b4a.z, b4a.w, b4b.x, b4b.y, b4b.z, b4b.w};
#pragma unroll
        for (int j = 0; j < 8; j++) {
            int kk = lc4 + (j >> 2) * 8 + (j & 3);
            unsigned h = f2tf(av[j]);
            Ah[kk][lr] = h;
            Al[kk][lr] = f2tf(av[j] - __uint_as_float(h));
            unsigned hb = f2tf(bv[j]);
            Bh_[kk][lr] = hb;
            Bl_[kk][lr] = f2tf(bv[j] - __uint_as_float(hb));
        }
        __syncthreads();

        if (k0 + 16 < DM) {
            int m = m0 + lr;
            if (AH) {
                int b = m >> 11, s = m & 2047;
                int k = k0 + 16 + lc4, h = k >> 6, dh = k & 63;
                a4a = *(const float4*)&A[(((size_t)(b * NH + h)) * SQ + s) * DH + dh];
                k += 8; h = k >> 6; dh = k & 63;
                a4b = *(const float4*)&A[(((size_t)(b * NH + h)) * SQ + s) * DH + dh];
            } else {
                a4a = *(const float4*)&A[(size_t)m * DM + k0 + 16 + lc4];
                a4b = *(const float4*)&A[(size_t)m * DM + k0 + 24 + lc4];
            }
            b4a = *(const float4*)&W[(size_t)(n0 + lr) * DM + k0 + 16 + lc4];
            b4b = *(const float4*)&W[(size_t)(n0 + lr) * DM + k0 + 24 + lc4];
        }

#pragma unroll
        for (int kc = 0; kc < 2; kc++) {
#pragma unroll
            for (int mt = 0; mt < 4; mt++) {
                int ra = wm0 + mt * 16 + g;
                unsigned ah[4] = {Ah[kc * 8 + t][ra],     Ah[kc * 8 + t][ra + 8],
                                  Ah[kc * 8 + t + 4][ra], Ah[kc * 8 + t + 4][ra + 8]};
                unsigned al[4] = {Al[kc * 8 + t][ra],     Al[kc * 8 + t][ra + 8],
                                  Al[kc * 8 + t + 4][ra], Al[kc * 8 + t + 4][ra + 8]};
#pragma unroll
                for (int nt = 0; nt < 4; nt++) {
                    int rb = wn0 + nt * 8 + g;
                    unsigned b0h = Bh_[kc * 8 + t][rb], b1h = Bh_[kc * 8 + t + 4][rb];
                    unsigned b0l = Bl_[kc * 8 + t][rb], b1l = Bl_[kc * 8 + t + 4][rb];
                    mma_tf32(acc[mt][nt], ah, b0h, b1h);
                    mma_tf32(acc[mt][nt], ah, b0l, b1l);
                    mma_tf32(acc[mt][nt], al, b0h, b1h);
                }
            }
        }
        __syncthreads();
    }

#pragma unroll
    for (int mt = 0; mt < 4; mt++) {
#pragma unroll
        for (int nt = 0; nt < 4; nt++) {
            int r = m0 + wm0 + mt * 16 + g;
            int cgl = n0 + wn0 + nt * 8 + 2 * t;
            float b0v = bias[cgl], b1v = bias[cgl + 1];
            float2 v0 = {acc[mt][nt][0] + b0v, acc[mt][nt][1] + b1v};
            float2 v1 = {acc[mt][nt][2] + b0v, acc[mt][nt][3] + b1v};
            if (OH) {
                int h = cgl >> 6, dh = cgl & 63;
                int b = r >> 11, s = r & 2047;
                *(float2*)&out[(((size_t)(b * NH + h)) * SQ + s) * DH + dh] = v0;
                b = (r + 8) >> 11; s = (r + 8) & 2047;
                *(float2*)&out[(((size_t)(b * NH + h)) * SQ + s) * DH + dh] = v1;
            } else {
                *(float2*)&out[(size_t)r * DM + cgl] = v0;
                *(float2*)&out[(size_t)(r + 8) * DM + cgl] = v1;
            }
        }
    }
}

// ---------------------------------------------------------------------------
// Pass 1: rowsum[bh, q] = sum_key exp(S)  (S = QK^T/8 + mask*-1e9, no max)
// CTA = (qtile 128, bh). 8 warps, each owns m16. Key chunks of 64.
// ---------------------------------------------------------------------------
__global__ __launch_bounds__(256) void attn_rowsum_kernel(
    const float* __restrict__ mask)
{
    extern __shared__ __align__(16) unsigned char dynraw[];
    float* Qs = (float*)dynraw;                         // 128*PADQ
    unsigned* Khi = (unsigned*)(Qs + 128 * PADQ);       // 64*PADQ
    unsigned* Klo = Khi + 64 * PADQ;
    float* ms = (float*)(Klo + 64 * PADQ);              // 64

    int bh = blockIdx.y, q0 = blockIdx.x * 128;
    int tid = threadIdx.x, w = tid >> 5, lane = tid & 31;
    int g = lane >> 2, t = lane & 3;
    const float* Q = g_qh + (size_t)bh * SQ * DH;
    const float* K = g_kh + (size_t)bh * SQ * DH;
    const float* mrow = mask + (size_t)(bh >> 4) * SQ;

#pragma unroll
    for (int j = 0; j < 8; j++) {
        int idx = tid + j * 256;
        int row = idx >> 4, c4 = (idx & 15) * 4;
        *(float4*)&Qs[row * PADQ + c4] =
            *(const float4*)&Q[(size_t)(q0 + row) * DH + c4];
    }
    __syncthreads();

    float qf[8][4];
    int r0q = (w * 16 + g) * PADQ, r1q = (w * 16 + g + 8) * PADQ;
#pragma unroll
    for (int kc = 0; kc < 8; kc++) {
        qf[kc][0] = Qs[r0q + kc * 8 + t];
        qf[kc][1] = Qs[r1q + kc * 8 + t];
        qf[kc][2] = Qs[r0q + kc * 8 + t + 4];
        qf[kc][3] = Qs[r1q + kc * 8 + t + 4];
    }

    float rs0 = 0.f, rs1 = 0.f;
    for (int c = 0; c < 32; c++) {
        int n0c = c * 64;
#pragma unroll
        for (int j = 0; j < 4; j++) {
            int idx = tid + j * 256;
            int row = idx >> 4, c4 = (idx & 15) * 4;
            float4 v = *(const float4*)&K[(size_t)(n0c + row) * DH + c4];
            unsigned h0 = f2tf(v.x), h1 = f2tf(v.y), h2 = f2tf(v.z), h3 = f2tf(v.w);
            uint4 hh = {h0, h1, h2, h3};
            uint4 ll = {f2tf(v.x - __uint_as_float(h0)),
                        f2tf(v.y - __uint_as_float(h1)),
                        f2tf(v.z - __uint_as_float(h2)),
                        f2tf(v.w - __uint_as_float(h3))};
            *(uint4*)&Khi[row * PADQ + c4] = hh;
            *(uint4*)&Klo[row * PADQ + c4] = ll;
        }
        if (tid < 64) ms[tid] = mrow[n0c + tid];
        __syncthreads();

        float sacc[8][4];
#pragma unroll
        for (int nt = 0; nt < 8; nt++)
#pragma unroll
            for (int l = 0; l < 4; l++) sacc[nt][l] = 0.f;

#pragma unroll
        for (int kc = 0; kc < 8; kc++) {
            unsigned ah[4], al[4];
#pragma unroll
            for (int i = 0; i < 4; i++) {
                ah[i] = f2tf(qf[kc][i]);
                al[i] = f2tf(qf[kc][i] - __uint_as_float(ah[i]));
            }
#pragma unroll
            for (int nt = 0; nt < 8; nt++) {
                int kb = (nt * 8 + g) * PADQ + kc * 8 + t;
                unsigned b0h = Khi[kb], b1h = Khi[kb + 4];
                unsigned b0l = Klo[kb], b1l = Klo[kb + 4];
                mma_tf32(sacc[nt], ah, b0h, b1h);
                mma_tf32(sacc[nt], ah, b0l, b1l);
                mma_tf32(sacc[nt], al, b0h, b1h);
            }
        }
#pragma unroll
        for (int nt = 0; nt < 8; nt++) {
            int cl = nt * 8 + 2 * t;
            float m0v = ms[cl] * (-1e9f), m1v = ms[cl + 1] * (-1e9f);
            rs0 += __expf(sacc[nt][0] * 0.125f + m0v);
            rs0 += __expf(sacc[nt][1] * 0.125f + m1v);
            rs1 += __expf(sacc[nt][2] * 0.125f + m0v);
            rs1 += __expf(sacc[nt][3] * 0.125f + m1v);
        }
        __syncthreads();
    }
    rs0 += __shfl_xor_sync(~0u, rs0, 1);
    rs0 += __shfl_xor_sync(~0u, rs0, 2);
    rs1 += __shfl_xor_sync(~0u, rs1, 1);
    rs1 += __shfl_xor_sync(~0u, rs1, 2);
    if (t == 0) {
        g_rowsum[(size_t)bh * SQ + q0 + w * 16 + g] = rs0;
        g_rowsum[(size_t)bh * SQ + q0 + w * 16 + g + 8] = rs1;
    }
}

// ---------------------------------------------------------------------------
// Pass 2: recompute S, write NORMALIZED attn once, accumulate O = attn @ V.
// ---------------------------------------------------------------------------
__global__ __launch_bounds__(256) void attn_av_kernel(
    const float* __restrict__ mask, float* __restrict__ attn)
{
    extern __shared__ __align__(16) unsigned char dynraw[];
    float* Qs = (float*)dynraw;                          // 128*PADQ
    unsigned* Khi = (unsigned*)(Qs + 128 * PADQ);        // 64*PADQ each
    unsigned* Klo = Khi + 64 * PADQ;
    unsigned* Vhi = Klo + 64 * PADQ;
    unsigned* Vlo = Vhi + 64 * PADQ;
    float* Ps = (float*)(Vlo + 64 * PADQ);               // 8*16*PADQ
    float* ms = Ps + 8 * 16 * PADQ;                      // 64
    float* invl = ms + 64;                               // 128

    int bh = blockIdx.y, q0 = blockIdx.x * 128;
    int tid = threadIdx.x, w = tid >> 5, lane = tid & 31;
    int g = lane >> 2, t = lane & 3;
    const float* Q = g_qh + (size_t)bh * SQ * DH;
    const float* K = g_kh + (size_t)bh * SQ * DH;
    const float* V = g_vh + (size_t)bh * SQ * DH;
    const float* mrow = mask + (size_t)(bh >> 4) * SQ;
    float* attn_b = attn + (size_t)bh * SQ * SQ;

#pragma unroll
    for (int j = 0; j < 8; j++) {
        int idx = tid + j * 256;
        int row = idx >> 4, c4 = (idx & 15) * 4;
        *(float4*)&Qs[row * PADQ + c4] =
            *(const float4*)&Q[(size_t)(q0 + row) * DH + c4];
    }
    if (tid < 128) invl[tid] = 1.0f / g_rowsum[(size_t)bh * SQ + q0 + tid];
    __syncthreads();

    float qf[8][4];
    {
        int r0q = (w * 16 + g) * PADQ, r1q = (w * 16 + g + 8) * PADQ;
#pragma unroll
        for (int kc = 0; kc < 8; kc++) {
            qf[kc][0] = Qs[r0q + kc * 8 + t];
            qf[kc][1] = Qs[r1q + kc * 8 + t];
            qf[kc][2] = Qs[r0q + kc * 8 + t + 4];
            qf[kc][3] = Qs[r1q + kc * 8 + t + 4];
        }
    }
    float il0 = invl[w * 16 + g], il1 = invl[w * 16 + g + 8];

    float oacc[8][4];
#pragma unroll
    for (int nt = 0; nt < 8; nt++)
#pragma unroll
        for (int l = 0; l < 4; l++) oacc[nt][l] = 0.f;

    float* Pw = Ps + w * 16 * PADQ;

    for (int c = 0; c < 32; c++) {
        int n0c = c * 64;
#pragma unroll
        for (int j = 0; j < 4; j++) {
            int idx = tid + j * 256;
            int row = idx >> 4, c4 = (idx & 15) * 4;
            float4 kv = *(const float4*)&K[(size_t)(n0c + row) * DH + c4];
            float4 vv = *(const float4*)&V[(size_t)(n0c + row) * DH + c4];
            unsigned kh0 = f2tf(kv.x), kh1 = f2tf(kv.y), kh2 = f2tf(kv.z), kh3 = f2tf(kv.w);
            unsigned vh0 = f2tf(vv.x), vh1 = f2tf(vv.y), vh2 = f2tf(vv.z), vh3 = f2tf(vv.w);
            uint4 khh = {kh0, kh1, kh2, kh3};
            uint4 kll = {f2tf(kv.x - __uint_as_float(kh0)),
                         f2tf(kv.y - __uint_as_float(kh1)),
                         f2tf(kv.z - __uint_as_float(kh2)),
                         f2tf(kv.w - __uint_as_float(kh3))};
            uint4 vhh = {vh0, vh1, vh2, vh3};
            uint4 vll = {f2tf(vv.x - __uint_as_float(vh0)),
                         f2tf(vv.y - __uint_as_float(vh1)),
                         f2tf(vv.z - __uint_as_float(vh2)),
                         f2tf(vv.w - __uint_as_float(vh3))};
            *(uint4*)&Khi[row * PADQ + c4] = khh;
            *(uint4*)&Klo[row * PADQ + c4] = kll;
            *(uint4*)&Vhi[row * PADQ + c4] = vhh;
            *(uint4*)&Vlo[row * PADQ + c4] = vll;
        }
        if (tid < 64) ms[tid] = mrow[n0c + tid];
        __syncthreads();

        // S = Q K^T (split 3-mma)
        float sacc[8][4];
#pragma unroll
        for (int nt = 0; nt < 8; nt++)
#pragma unroll
            for (int l = 0; l < 4; l++) sacc[nt][l] = 0.f;

#pragma unroll
        for (int kc = 0; kc < 8; kc++) {
            unsigned ah[4], al[4];
#pragma unroll
            for (int i = 0; i < 4; i++) {
                ah[i] = f2tf(qf[kc][i]);
                al[i] = f2tf(qf[kc][i] - __uint_as_float(ah[i]));
            }
#pragma unroll
            for (int nt = 0; nt < 8; nt++) {
                int kb = (nt * 8 + g) * PADQ + kc * 8 + t;
                unsigned b0h = Khi[kb], b1h = Khi[kb + 4];
                unsigned b0l = Klo[kb], b1l = Klo[kb + 4];
                mma_tf32(sacc[nt], ah, b0h, b1h);
                mma_tf32(sacc[nt], ah, b0l, b1l);
                mma_tf32(sacc[nt], al, b0h, b1h);
            }
        }

        // p = exp(S/8 + mask)*invl ; write attn + stage to smem for AV mma
        int row0 = q0 + w * 16 + g;
#pragma unroll
        for (int nt = 0; nt < 8; nt++) {
            int cl = nt * 8 + 2 * t;
            float m0v = ms[cl] * (-1e9f), m1v = ms[cl + 1] * (-1e9f);
            float p00 = __expf(sacc[nt][0] * 0.125f + m0v) * il0;
            float p01 = __expf(sacc[nt][1] * 0.125f + m1v) * il0;
            float p10 = __expf(sacc[nt][2] * 0.125f + m0v) * il1;
            float p11 = __expf(sacc[nt][3] * 0.125f + m1v) * il1;
            int gcol = n0c + cl;
            float2 v0 = {p00, p01};
            float2 v1 = {p10, p11};
            *(float2*)&attn_b[(size_t)row0 * SQ + gcol] = v0;
            *(float2*)&attn_b[(size_t)(row0 + 8) * SQ + gcol] = v1;
            Pw[g * PADQ + cl] = p00;
            Pw[g * PADQ + cl + 1] = p01;
            Pw[(g + 8) * PADQ + cl] = p10;
            Pw[(g + 8) * PADQ + cl + 1] = p11;
        }
        __syncwarp();

        // O += p @ V  (p single tf32, V split)
#pragma unroll
        for (int kc = 0; kc < 8; kc++) {
            unsigned ph[4];
            ph[0] = f2tf(Pw[g * PADQ + kc * 8 + t]);
            ph[1] = f2tf(Pw[(g + 8) * PADQ + kc * 8 + t]);
            ph[2] = f2tf(Pw[g * PADQ + kc * 8 + t + 4]);
            ph[3] = f2tf(Pw[(g + 8) * PADQ + kc * 8 + t + 4]);
#pragma unroll
            for (int nt = 0; nt < 8; nt++) {
                int vb = (kc * 8 + t) * PADQ + nt * 8 + g;
                unsigned b0h = Vhi[vb], b1h = Vhi[vb + 4 * PADQ];
                unsigned b0l = Vlo[vb], b1l = Vlo[vb + 4 * PADQ];
                mma_tf32(oacc[nt], ph, b0h, b1h);
                mma_tf32(oacc[nt], ph, b0l, b1l);
            }
        }
        __syncthreads();
    }

    // write O (already normalized) to ctx head-layout
    float* C = g_ctx + (size_t)bh * SQ * DH;
    int row0 = q0 + w * 16 + g;
#pragma unroll
    for (int nt = 0; nt < 8; nt++) {
        int dh0 = nt * 8 + 2 * t;
        float2 v0 = {oacc[nt][0], oacc[nt][1]};
        float2 v1 = {oacc[nt][2], oacc[nt][3]};
        *(float2*)&C[(size_t)row0 * DH + dh0] = v0;
        *(float2*)&C[(size_t)(row0 + 8) * DH + dh0] = v1;
    }
}

// ---------------------------------------------------------------------------
extern "C" void kernel_launch(void* const* d_in, const int* in_sizes, int n_in,
                              void* d_out, int out_size)
{
    const float* q    = (const float*)d_in[0];
    const float* k    = (const float*)d_in[1];
    const float* v    = (const float*)d_in[2];
    const float* mask = (const float*)d_in[3];
    const float* wq   = (const float*)d_in[4];
    const float* bq   = (const float*)d_in[5];
    const float* wk   = (const float*)d_in[6];
    const float* bk   = (const float*)d_in[7];
    const float* wv   = (const float*)d_in[8];
    const float* bv   = (const float*)d_in[9];
    const float* wo   = (const float*)d_in[10];
    const float* bo   = (const float*)d_in[11];

    float* out  = (float*)d_out;
    float* attn = out + (size_t)NB * SQ * DM;

    float *qh, *kh, *vh, *ctx;
    cudaGetSymbolAddress((void**)&qh,  g_qh);
    cudaGetSymbolAddress((void**)&kh,  g_kh);
    cudaGetSymbolAddress((void**)&vh,  g_vh);
    cudaGetSymbolAddress((void**)&ctx, g_ctx);

    // dynamic smem sizes
    const int SM_RS = (128 * PADQ) * 4 + 2 * (64 * PADQ) * 4 + 64 * 4;
    const int SM_AV = (128 * PADQ) * 4 + 4 * (64 * PADQ) * 4 +
                      (8 * 16 * PADQ) * 4 + 64 * 4 + 128 * 4;
    static bool attr_done = false;
    if (!attr_done) {
        cudaFuncSetAttribute(attn_rowsum_kernel,
                             cudaFuncAttributeMaxDynamicSharedMemorySize, SM_RS);
        cudaFuncSetAttribute(attn_av_kernel,
                             cudaFuncAttributeMaxDynamicSharedMemorySize, SM_AV);
        attr_done = true;
    }

    dim3 gProj(DM / 128, MTOT / 128);       // (8, 32)
    proj_tf32<false, true><<<gProj, 256>>>(q, wq, bq, qh);
    proj_tf32<false, true><<<gProj, 256>>>(k, wk, bk, kh);
    proj_tf32<false, true><<<gProj, 256>>>(v, wv, bv, vh);

    dim3 gAtt(SQ / 128, BH);                // (16, 32)
    attn_rowsum_kernel<<<gAtt, 256, SM_RS>>>(mask);
    attn_av_kernel<<<gAtt, 256, SM_AV>>>(mask, attn);

    proj_tf32<true, false><<<gProj, 256>>>(ctx, wo, bo, out);
}